// round 2
// baseline (speedup 1.0000x reference)
#include <cuda_runtime.h>
#include <cuda_bf16.h>
#include <math.h>

#define NN 50000
#define EE 800000
#define HID 128
#define BGR 64

// ---------------- scratch (static __device__, no allocation) ----------------
__device__ float g_Q[NN * HID];
__device__ float g_K[NN * HID];
__device__ float g_V[NN * HID];
__device__ float g_S[NN * HID];
__device__ float g_H1[NN * HID];
__device__ float g_H2[NN * HID];

__device__ int g_rowstart[NN + 1];
__device__ int g_cnt[NN];
__device__ int g_fill[NN];
__device__ int g_src[EE];

__device__ float g_gsum[BGR * HID];
__device__ float g_gmax[BGR * HID];

// ---------------- init ----------------
__global__ void k_init() {
    int i = blockIdx.x * blockDim.x + threadIdx.x;
    if (i < NN) { g_cnt[i] = 0; g_fill[i] = 0; }
    if (i < BGR * HID) { g_gsum[i] = 0.f; g_gmax[i] = 0.f; }
}

// ---------------- CSR build ----------------
__global__ void k_hist(const int* __restrict__ ei) {
    int e = blockIdx.x * blockDim.x + threadIdx.x;
    if (e < EE) atomicAdd(&g_cnt[ei[EE + e]], 1);   // dst
}

__global__ void k_scan() {
    __shared__ int buf[1024];
    __shared__ int carry;
    int t = threadIdx.x;
    if (t == 0) carry = 0;
    __syncthreads();
    for (int base = 0; base < NN; base += 1024) {
        int i = base + t;
        int v = (i < NN) ? g_cnt[i] : 0;
        buf[t] = v;
        __syncthreads();
        for (int off = 1; off < 1024; off <<= 1) {
            int add = (t >= off) ? buf[t - off] : 0;
            __syncthreads();
            buf[t] += add;
            __syncthreads();
        }
        if (i < NN) g_rowstart[i] = carry + buf[t] - v;  // exclusive
        __syncthreads();
        if (t == 0) carry += buf[1023];
        __syncthreads();
    }
    if (t == 0) g_rowstart[NN] = carry;
}

__global__ void k_fill(const int* __restrict__ ei) {
    int e = blockIdx.x * blockDim.x + threadIdx.x;
    if (e < EE) {
        int d = ei[EE + e];
        int pos = g_rowstart[d] + atomicAdd(&g_fill[d], 1);
        g_src[pos] = ei[e];   // src
    }
}

// ---------------- fused 4-weight SGEMM: out = X @ W + b ----------------
// X: [NN,128], W: [128,128], per-block tile 128x128, BK=32, 256 thr, 8x8/thread.
// blockIdx.y selects (W,b,out) among Q,K,V,S. layer2 != 0 -> X = g_H1.
__global__ __launch_bounds__(256) void k_gemm4(
    const float* __restrict__ Xin, int layer2,
    const float* __restrict__ W0, const float* __restrict__ B0,
    const float* __restrict__ W1, const float* __restrict__ B1,
    const float* __restrict__ W2, const float* __restrict__ B2,
    const float* __restrict__ W3, const float* __restrict__ B3)
{
    __shared__ float As[32][128];
    __shared__ float Bs[32][128];

    const float* X = layer2 ? (const float*)g_H1 : Xin;

    const float* W; const float* Bb; float* Out;
    switch (blockIdx.y) {
        case 0:  W = W0; Bb = B0; Out = g_Q; break;
        case 1:  W = W1; Bb = B1; Out = g_K; break;
        case 2:  W = W2; Bb = B2; Out = g_V; break;
        default: W = W3; Bb = B3; Out = g_S; break;
    }

    int row0 = blockIdx.x * 128;
    int tid = threadIdx.x;
    int tx = tid & 15, ty = tid >> 4;

    float acc[8][8];
    #pragma unroll
    for (int i = 0; i < 8; i++)
        #pragma unroll
        for (int j = 0; j < 8; j++) acc[i][j] = 0.f;

    for (int k0 = 0; k0 < 128; k0 += 32) {
        // A tile: 128 rows x 32 k, stored transposed As[k][m]
        #pragma unroll
        for (int i = 0; i < 4; i++) {
            int lin = tid + i * 256;      // 0..1023 float4 slots
            int m = lin >> 3;
            int kq = (lin & 7) * 4;
            float4 v = make_float4(0.f, 0.f, 0.f, 0.f);
            int gm = row0 + m;
            if (gm < NN) v = *(const float4*)(X + gm * 128 + k0 + kq);
            As[kq + 0][m] = v.x; As[kq + 1][m] = v.y;
            As[kq + 2][m] = v.z; As[kq + 3][m] = v.w;
        }
        // B tile: 32 k x 128 n
        #pragma unroll
        for (int i = 0; i < 4; i++) {
            int lin4 = tid + i * 256;     // float4 index
            int kq = lin4 >> 5;
            int n = (lin4 & 31) * 4;
            *(float4*)&Bs[kq][n] = *(const float4*)(W + (k0 + kq) * 128 + n);
        }
        __syncthreads();

        #pragma unroll
        for (int kk = 0; kk < 32; kk++) {
            float a[8], b[8];
            *(float4*)(a)     = *(float4*)&As[kk][ty * 8];
            *(float4*)(a + 4) = *(float4*)&As[kk][ty * 8 + 4];
            *(float4*)(b)     = *(float4*)&Bs[kk][tx * 8];
            *(float4*)(b + 4) = *(float4*)&Bs[kk][tx * 8 + 4];
            #pragma unroll
            for (int i = 0; i < 8; i++)
                #pragma unroll
                for (int j = 0; j < 8; j++)
                    acc[i][j] = fmaf(a[i], b[j], acc[i][j]);
        }
        __syncthreads();
    }

    float bias[8];
    *(float4*)(bias)     = *(const float4*)(Bb + tx * 8);
    *(float4*)(bias + 4) = *(const float4*)(Bb + tx * 8 + 4);

    #pragma unroll
    for (int i = 0; i < 8; i++) {
        int gm = row0 + ty * 8 + i;
        if (gm < NN) {
            float4 o0, o1;
            o0.x = acc[i][0] + bias[0]; o0.y = acc[i][1] + bias[1];
            o0.z = acc[i][2] + bias[2]; o0.w = acc[i][3] + bias[3];
            o1.x = acc[i][4] + bias[4]; o1.y = acc[i][5] + bias[5];
            o1.z = acc[i][6] + bias[6]; o1.w = acc[i][7] + bias[7];
            *(float4*)(Out + gm * 128 + tx * 8)     = o0;
            *(float4*)(Out + gm * 128 + tx * 8 + 4) = o1;
        }
    }
}

// ---------------- attention: one warp per dst node, online softmax ----------
// out_sel: 0 -> g_H1, 1 -> g_H2
__global__ __launch_bounds__(256) void k_attn(int out_sel)
{
    int gw = (blockIdx.x * blockDim.x + threadIdx.x) >> 5;
    int lane = threadIdx.x & 31;
    if (gw >= NN) return;
    const int i = gw;
    const int co = lane * 4;        // lane's 4 channels; head = lane/8

    const float* __restrict__ Qb = g_Q;
    const float* __restrict__ Kb = g_K;
    const float* __restrict__ Vb = g_V;
    const float* __restrict__ Sb = g_S;
    float* __restrict__ Hb = out_sel ? g_H2 : g_H1;

    float4 q = *(const float4*)(Qb + i * 128 + co);
    int e0 = g_rowstart[i], e1 = g_rowstart[i + 1];

    float m = -1e30f, s = 0.f;
    float4 acc = make_float4(0.f, 0.f, 0.f, 0.f);
    const float rsC = 0.17677669529663687f;   // 1/sqrt(32)

    if (e0 < e1) {
        int src = g_src[e0];
        float4 kv = *(const float4*)(Kb + src * 128 + co);
        float4 vv = *(const float4*)(Vb + src * 128 + co);
        for (int e = e0; e < e1; e++) {
            float4 nk = kv, nv = vv;
            if (e + 1 < e1) {                       // prefetch next edge
                int ns = g_src[e + 1];
                nk = *(const float4*)(Kb + ns * 128 + co);
                nv = *(const float4*)(Vb + ns * 128 + co);
            }
            float p = q.x * kv.x + q.y * kv.y + q.z * kv.z + q.w * kv.w;
            p += __shfl_xor_sync(0xffffffffu, p, 1);
            p += __shfl_xor_sync(0xffffffffu, p, 2);
            p += __shfl_xor_sync(0xffffffffu, p, 4);   // 8-lane head reduce
            float alpha = p * rsC;
            float nm = fmaxf(m, alpha);
            float sc = __expf(m - nm);
            float w  = __expf(alpha - nm);
            s = s * sc + w;
            acc.x = fmaf(w, vv.x, acc.x * sc);
            acc.y = fmaf(w, vv.y, acc.y * sc);
            acc.z = fmaf(w, vv.z, acc.z * sc);
            acc.w = fmaf(w, vv.w, acc.w * sc);
            m = nm;
            kv = nk; vv = nv;
        }
    }

    float inv = 1.f / (s + 1e-16f);
    float4 sk = *(const float4*)(Sb + i * 128 + co);
    float4 o;
    o.x = fmaxf(fmaf(acc.x, inv, sk.x), 0.f);
    o.y = fmaxf(fmaf(acc.y, inv, sk.y), 0.f);
    o.z = fmaxf(fmaf(acc.z, inv, sk.z), 0.f);
    o.w = fmaxf(fmaf(acc.w, inv, sk.w), 0.f);
    *(float4*)(Hb + i * 128 + co) = o;
}

// ---------------- pooling: batch is sorted; thread = channel ----------------
__global__ void k_pool(const int* __restrict__ batch) {
    int t = threadIdx.x;                 // 0..127
    int n0 = blockIdx.x * 512;
    if (n0 >= NN) return;
    int n1 = n0 + 512; if (n1 > NN) n1 = NN;
    const float* __restrict__ Hf = g_H2;

    int cur = batch[n0];
    float sum = 0.f, mx = 0.f;
    for (int n = n0; n < n1; n++) {
        int b = batch[n];
        if (b != cur) {
            atomicAdd(&g_gsum[cur * 128 + t], sum);
            atomicMax((int*)&g_gmax[cur * 128 + t], __float_as_int(mx));
            sum = 0.f; mx = 0.f; cur = b;
        }
        float v = Hf[n * 128 + t];
        sum += v; mx = fmaxf(mx, v);
    }
    atomicAdd(&g_gsum[cur * 128 + t], sum);
    atomicMax((int*)&g_gmax[cur * 128 + t], __float_as_int(mx));
}

// ---------------- classifier: out[b,c] = concat(gsum,gmax) @ Wlin + blin ----
__global__ void k_cls(const float* __restrict__ Wlin, const float* __restrict__ blin,
                      float* __restrict__ out) {
    int t = threadIdx.x;
    if (t >= 128) return;
    int b = t >> 1, c = t & 1;
    float acc = blin[c];
    for (int j = 0; j < 128; j++) acc = fmaf(g_gsum[b * 128 + j], Wlin[j * 2 + c], acc);
    for (int j = 0; j < 128; j++) acc = fmaf(g_gmax[b * 128 + j], Wlin[(128 + j) * 2 + c], acc);
    out[b * 2 + c] = acc;
}

// ---------------- launch ----------------
extern "C" void kernel_launch(void* const* d_in, const int* in_sizes, int n_in,
                              void* d_out, int out_size)
{
    const float* x   = (const float*)d_in[0];
    const int* ei    = (const int*)d_in[1];
    const int* batch = (const int*)d_in[2];
    const float* Wq1 = (const float*)d_in[3];  const float* bq1 = (const float*)d_in[4];
    const float* Wk1 = (const float*)d_in[5];  const float* bk1 = (const float*)d_in[6];
    const float* Wv1 = (const float*)d_in[7];  const float* bv1 = (const float*)d_in[8];
    const float* Ws1 = (const float*)d_in[9];  const float* bs1 = (const float*)d_in[10];
    const float* Wq2 = (const float*)d_in[11]; const float* bq2 = (const float*)d_in[12];
    const float* Wk2 = (const float*)d_in[13]; const float* bk2 = (const float*)d_in[14];
    const float* Wv2 = (const float*)d_in[15]; const float* bv2 = (const float*)d_in[16];
    const float* Ws2 = (const float*)d_in[17]; const float* bs2 = (const float*)d_in[18];
    const float* Wlin = (const float*)d_in[19]; const float* blin = (const float*)d_in[20];
    float* out = (float*)d_out;

    // CSR build + scratch init
    k_init<<<(NN + 255) / 256, 256>>>();
    k_hist<<<(EE + 255) / 256, 256>>>(ei);
    k_scan<<<1, 1024>>>();
    k_fill<<<(EE + 255) / 256, 256>>>(ei);

    dim3 gg((NN + 127) / 128, 4);

    // layer 1
    k_gemm4<<<gg, 256>>>(x, 0, Wq1, bq1, Wk1, bk1, Wv1, bv1, Ws1, bs1);
    k_attn<<<(NN + 7) / 8, 256>>>(0);

    // layer 2
    k_gemm4<<<gg, 256>>>(x, 1, Wq2, bq2, Wk2, bk2, Wv2, bv2, Ws2, bs2);
    k_attn<<<(NN + 7) / 8, 256>>>(1);

    // pooling + classifier
    k_pool<<<(NN + 511) / 512, 128>>>(batch);
    k_cls<<<1, 128>>>(Wlin, blin, out);
}

// round 3
// speedup vs baseline: 1.4689x; 1.4689x over previous
#include <cuda_runtime.h>
#include <cuda_bf16.h>
#include <math.h>

#define NN 50000
#define EE 800000
#define HID 128
#define BGR 64

// ---------------- scratch (static __device__, no allocation) ----------------
__device__ float g_Q[NN * HID];
__device__ float g_K[NN * HID];
__device__ float g_V[NN * HID];
__device__ float g_S[NN * HID];
__device__ float g_H1[NN * HID];
__device__ float g_H2[NN * HID];

__device__ int g_rowstart[NN + 1];
__device__ int g_cnt[NN];
__device__ int g_fill[NN];
__device__ int g_src[EE];

__device__ float g_gsum[BGR * HID];
__device__ float g_gmax[BGR * HID];

// ---------------- helpers ----------------
__device__ __forceinline__ unsigned f2tf(float x) {
    unsigned u;
    asm("cvt.rna.tf32.f32 %0, %1;" : "=r"(u) : "f"(x));
    return u;
}

__device__ __forceinline__ void mma_tf32(float (&d)[4], const unsigned (&a)[4],
                                         const unsigned (&b)[2]) {
    asm volatile(
        "mma.sync.aligned.m16n8k8.row.col.f32.tf32.tf32.f32 "
        "{%0,%1,%2,%3}, {%4,%5,%6,%7}, {%8,%9}, {%0,%1,%2,%3};\n"
        : "+f"(d[0]), "+f"(d[1]), "+f"(d[2]), "+f"(d[3])
        : "r"(a[0]), "r"(a[1]), "r"(a[2]), "r"(a[3]), "r"(b[0]), "r"(b[1]));
}

// ---------------- init ----------------
__global__ void k_init() {
    int i = blockIdx.x * blockDim.x + threadIdx.x;
    if (i < NN) { g_cnt[i] = 0; g_fill[i] = 0; }
    if (i < BGR * HID) { g_gsum[i] = 0.f; g_gmax[i] = 0.f; }
}

// ---------------- CSR build ----------------
__global__ void k_hist(const int* __restrict__ ei) {
    int e = blockIdx.x * blockDim.x + threadIdx.x;
    if (e < EE) atomicAdd(&g_cnt[ei[EE + e]], 1);   // dst
}

// shfl-based block scan: 1024 threads, 3 syncthreads per 1024-tile
__global__ void k_scan() {
    __shared__ int wsum[32];
    __shared__ int carry;
    int t = threadIdx.x, lane = t & 31, w = t >> 5;
    if (t == 0) carry = 0;
    __syncthreads();
    for (int base = 0; base < NN; base += 1024) {
        int i = base + t;
        int v = (i < NN) ? g_cnt[i] : 0;
        int sv = v;
        #pragma unroll
        for (int off = 1; off < 32; off <<= 1) {
            int n = __shfl_up_sync(0xffffffffu, sv, off);
            if (lane >= off) sv += n;
        }
        if (lane == 31) wsum[w] = sv;
        __syncthreads();
        if (w == 0) {
            int s = wsum[lane];
            #pragma unroll
            for (int off = 1; off < 32; off <<= 1) {
                int n = __shfl_up_sync(0xffffffffu, s, off);
                if (lane >= off) s += n;
            }
            wsum[lane] = s;
        }
        __syncthreads();
        int pre = (w > 0) ? wsum[w - 1] : 0;
        int tot = wsum[31];
        if (i < NN) g_rowstart[i] = carry + pre + sv - v;  // exclusive
        __syncthreads();
        if (t == 0) carry += tot;
    }
    __syncthreads();
    if (t == 0) g_rowstart[NN] = carry;
}

__global__ void k_fill(const int* __restrict__ ei) {
    int e = blockIdx.x * blockDim.x + threadIdx.x;
    if (e < EE) {
        int d = ei[EE + e];
        int pos = g_rowstart[d] + atomicAdd(&g_fill[d], 1);
        g_src[pos] = ei[e];   // src
    }
}

// ---------------- fused 4-weight tf32 tensor-core GEMM ----------------
// out = X @ W + b.  X:[NN,128], W:[128,128].  Block tile 128x128, 256 thr,
// 8 warps in 4x2 arrangement, warp tile 32x64, mma m16n8k8 tf32.
// blockIdx.y selects (W,b,out) among Q,K,V,S. layer2 != 0 -> X = g_H1.
__global__ __launch_bounds__(256) void k_gemm4_tc(
    const float* __restrict__ Xin, int layer2,
    const float* __restrict__ W0, const float* __restrict__ B0,
    const float* __restrict__ W1, const float* __restrict__ B1,
    const float* __restrict__ W2, const float* __restrict__ B2,
    const float* __restrict__ W3, const float* __restrict__ B3)
{
    __shared__ unsigned As[128][36];    // 128 rows x 32 k (pad 36: banks 4r+c)
    __shared__ unsigned Bsm[32][136];   // 32 k x 128 n   (pad 136: banks 8k+n)

    const float* X = layer2 ? (const float*)g_H1 : Xin;

    const float* W; const float* Bb; float* Out;
    switch (blockIdx.y) {
        case 0:  W = W0; Bb = B0; Out = g_Q; break;
        case 1:  W = W1; Bb = B1; Out = g_K; break;
        case 2:  W = W2; Bb = B2; Out = g_V; break;
        default: W = W3; Bb = B3; Out = g_S; break;
    }

    const int row0 = blockIdx.x * 128;
    const int tid = threadIdx.x;
    const int lane = tid & 31;
    const int w = tid >> 5;
    const int wm = w >> 1;       // 0..3 : row block of 32
    const int wn = w & 1;        // 0..1 : col block of 64
    const int g = lane >> 2;     // groupID 0..7
    const int tig = lane & 3;    // thread-in-group 0..3

    float acc[2][8][4];
    #pragma unroll
    for (int a = 0; a < 2; a++)
        #pragma unroll
        for (int b = 0; b < 8; b++)
            #pragma unroll
            for (int c = 0; c < 4; c++) acc[a][b][c] = 0.f;

    for (int k0 = 0; k0 < 128; k0 += 32) {
        // stage A tile (128x32) as tf32
        #pragma unroll
        for (int i = 0; i < 4; i++) {
            int lin = tid + i * 256;          // float4 slot 0..1023
            int m = lin >> 3;
            int kq = (lin & 7) * 4;
            int gm = row0 + m;
            float4 v = make_float4(0.f, 0.f, 0.f, 0.f);
            if (gm < NN) v = *(const float4*)(X + gm * 128 + k0 + kq);
            uint4 u;
            u.x = f2tf(v.x); u.y = f2tf(v.y); u.z = f2tf(v.z); u.w = f2tf(v.w);
            *(uint4*)&As[m][kq] = u;
        }
        // stage B tile (32x128) as tf32
        #pragma unroll
        for (int i = 0; i < 4; i++) {
            int lin = tid + i * 256;
            int kq = lin >> 5;
            int n4 = (lin & 31) * 4;
            float4 v = *(const float4*)(W + (k0 + kq) * 128 + n4);
            uint4 u;
            u.x = f2tf(v.x); u.y = f2tf(v.y); u.z = f2tf(v.z); u.w = f2tf(v.w);
            *(uint4*)&Bsm[kq][n4] = u;
        }
        __syncthreads();

        #pragma unroll
        for (int kk = 0; kk < 32; kk += 8) {
            unsigned a[2][4];
            #pragma unroll
            for (int mt = 0; mt < 2; mt++) {
                int r = wm * 32 + mt * 16;
                a[mt][0] = As[r + g][kk + tig];
                a[mt][1] = As[r + g + 8][kk + tig];
                a[mt][2] = As[r + g][kk + tig + 4];
                a[mt][3] = As[r + g + 8][kk + tig + 4];
            }
            #pragma unroll
            for (int nt = 0; nt < 8; nt++) {
                unsigned b[2];
                int c = wn * 64 + nt * 8 + g;
                b[0] = Bsm[kk + tig][c];
                b[1] = Bsm[kk + tig + 4][c];
                mma_tf32(acc[0][nt], a[0], b);
                mma_tf32(acc[1][nt], a[1], b);
            }
        }
        __syncthreads();
    }

    // epilogue: add bias, store float2 pairs
    #pragma unroll
    for (int nt = 0; nt < 8; nt++) {
        int col = wn * 64 + nt * 8 + 2 * tig;
        float2 bias2 = *(const float2*)(Bb + col);
        #pragma unroll
        for (int mt = 0; mt < 2; mt++) {
            int r0 = row0 + wm * 32 + mt * 16 + g;
            int r1 = r0 + 8;
            if (r0 < NN) {
                float2 o;
                o.x = acc[mt][nt][0] + bias2.x;
                o.y = acc[mt][nt][1] + bias2.y;
                *(float2*)(Out + r0 * 128 + col) = o;
            }
            if (r1 < NN) {
                float2 o;
                o.x = acc[mt][nt][2] + bias2.x;
                o.y = acc[mt][nt][3] + bias2.y;
                *(float2*)(Out + r1 * 128 + col) = o;
            }
        }
    }
}

// ---------------- attention: one warp per dst node, online softmax ----------
// out_sel: 0 -> g_H1, 1 -> g_H2
__global__ __launch_bounds__(256) void k_attn(int out_sel)
{
    int gw = (blockIdx.x * blockDim.x + threadIdx.x) >> 5;
    int lane = threadIdx.x & 31;
    if (gw >= NN) return;
    const int i = gw;
    const int co = lane * 4;        // lane's 4 channels; head = lane/8

    const float* __restrict__ Qb = g_Q;
    const float* __restrict__ Kb = g_K;
    const float* __restrict__ Vb = g_V;
    const float* __restrict__ Sb = g_S;
    float* __restrict__ Hb = out_sel ? g_H2 : g_H1;

    float4 q = *(const float4*)(Qb + i * 128 + co);
    int e0 = g_rowstart[i], e1 = g_rowstart[i + 1];

    float m = -1e30f, s = 0.f;
    float4 acc = make_float4(0.f, 0.f, 0.f, 0.f);
    const float rsC = 0.17677669529663687f;   // 1/sqrt(32)

    if (e0 < e1) {
        int src = g_src[e0];
        float4 kv = *(const float4*)(Kb + src * 128 + co);
        float4 vv = *(const float4*)(Vb + src * 128 + co);
        for (int e = e0; e < e1; e++) {
            float4 nk = kv, nv = vv;
            if (e + 1 < e1) {                       // prefetch next edge
                int ns = g_src[e + 1];
                nk = *(const float4*)(Kb + ns * 128 + co);
                nv = *(const float4*)(Vb + ns * 128 + co);
            }
            float p = q.x * kv.x + q.y * kv.y + q.z * kv.z + q.w * kv.w;
            p += __shfl_xor_sync(0xffffffffu, p, 1);
            p += __shfl_xor_sync(0xffffffffu, p, 2);
            p += __shfl_xor_sync(0xffffffffu, p, 4);   // 8-lane head reduce
            float alpha = p * rsC;
            float nm = fmaxf(m, alpha);
            float sc = __expf(m - nm);
            float wgt = __expf(alpha - nm);
            s = s * sc + wgt;
            acc.x = fmaf(wgt, vv.x, acc.x * sc);
            acc.y = fmaf(wgt, vv.y, acc.y * sc);
            acc.z = fmaf(wgt, vv.z, acc.z * sc);
            acc.w = fmaf(wgt, vv.w, acc.w * sc);
            m = nm;
            kv = nk; vv = nv;
        }
    }

    float inv = 1.f / (s + 1e-16f);
    float4 sk = *(const float4*)(Sb + i * 128 + co);
    float4 o;
    o.x = fmaxf(fmaf(acc.x, inv, sk.x), 0.f);
    o.y = fmaxf(fmaf(acc.y, inv, sk.y), 0.f);
    o.z = fmaxf(fmaf(acc.z, inv, sk.z), 0.f);
    o.w = fmaxf(fmaf(acc.w, inv, sk.w), 0.f);
    *(float4*)(Hb + i * 128 + co) = o;
}

// ---------------- pooling: batch is sorted; thread = channel ----------------
__global__ void k_pool(const int* __restrict__ batch) {
    int t = threadIdx.x;                 // 0..127
    int n0 = blockIdx.x * 512;
    if (n0 >= NN) return;
    int n1 = n0 + 512; if (n1 > NN) n1 = NN;
    const float* __restrict__ Hf = g_H2;

    int cur = batch[n0];
    float sum = 0.f, mx = 0.f;
    for (int n = n0; n < n1; n++) {
        int b = batch[n];
        if (b != cur) {
            atomicAdd(&g_gsum[cur * 128 + t], sum);
            atomicMax((int*)&g_gmax[cur * 128 + t], __float_as_int(mx));
            sum = 0.f; mx = 0.f; cur = b;
        }
        float v = Hf[n * 128 + t];
        sum += v; mx = fmaxf(mx, v);
    }
    atomicAdd(&g_gsum[cur * 128 + t], sum);
    atomicMax((int*)&g_gmax[cur * 128 + t], __float_as_int(mx));
}

// ---------------- classifier ----------------
__global__ void k_cls(const float* __restrict__ Wlin, const float* __restrict__ blin,
                      float* __restrict__ out) {
    int t = threadIdx.x;
    if (t >= 128) return;
    int b = t >> 1, c = t & 1;
    float acc = blin[c];
    for (int j = 0; j < 128; j++) acc = fmaf(g_gsum[b * 128 + j], Wlin[j * 2 + c], acc);
    for (int j = 0; j < 128; j++) acc = fmaf(g_gmax[b * 128 + j], Wlin[(128 + j) * 2 + c], acc);
    out[b * 2 + c] = acc;
}

// ---------------- launch ----------------
extern "C" void kernel_launch(void* const* d_in, const int* in_sizes, int n_in,
                              void* d_out, int out_size)
{
    const float* x   = (const float*)d_in[0];
    const int* ei    = (const int*)d_in[1];
    const int* batch = (const int*)d_in[2];
    const float* Wq1 = (const float*)d_in[3];  const float* bq1 = (const float*)d_in[4];
    const float* Wk1 = (const float*)d_in[5];  const float* bk1 = (const float*)d_in[6];
    const float* Wv1 = (const float*)d_in[7];  const float* bv1 = (const float*)d_in[8];
    const float* Ws1 = (const float*)d_in[9];  const float* bs1 = (const float*)d_in[10];
    const float* Wq2 = (const float*)d_in[11]; const float* bq2 = (const float*)d_in[12];
    const float* Wk2 = (const float*)d_in[13]; const float* bk2 = (const float*)d_in[14];
    const float* Wv2 = (const float*)d_in[15]; const float* bv2 = (const float*)d_in[16];
    const float* Ws2 = (const float*)d_in[17]; const float* bs2 = (const float*)d_in[18];
    const float* Wlin = (const float*)d_in[19]; const float* blin = (const float*)d_in[20];
    float* out = (float*)d_out;

    // CSR build + scratch init
    k_init<<<(NN + 255) / 256, 256>>>();
    k_hist<<<(EE + 255) / 256, 256>>>(ei);
    k_scan<<<1, 1024>>>();
    k_fill<<<(EE + 255) / 256, 256>>>(ei);

    dim3 gg((NN + 127) / 128, 4);

    // layer 1
    k_gemm4_tc<<<gg, 256>>>(x, 0, Wq1, bq1, Wk1, bk1, Wv1, bv1, Ws1, bs1);
    k_attn<<<(NN + 7) / 8, 256>>>(0);

    // layer 2
    k_gemm4_tc<<<gg, 256>>>(x, 1, Wq2, bq2, Wk2, bk2, Wv2, bv2, Ws2, bs2);
    k_attn<<<(NN + 7) / 8, 256>>>(1);

    // pooling + classifier
    k_pool<<<(NN + 511) / 512, 128>>>(batch);
    k_cls<<<1, 128>>>(Wlin, blin, out);
}

// round 4
// speedup vs baseline: 1.5943x; 1.0854x over previous
#include <cuda_runtime.h>
#include <cuda_bf16.h>
#include <math.h>

#define NN 50000
#define EE 800000
#define HID 128
#define BGR 64

// ---------------- scratch (static __device__, no allocation) ----------------
__device__ float g_Q[NN * HID];
__device__ float g_K[NN * HID];
__device__ float g_V[NN * HID];
__device__ float g_S[NN * HID];
__device__ float g_H1[NN * HID];
__device__ float g_H2[NN * HID];

__device__ int g_rowstart[NN + 1];
__device__ int g_cnt[NN];
__device__ int g_fill[NN];
__device__ int g_src[EE];
__device__ int g_blocksum[64];

__device__ float g_gsum[BGR * HID];
__device__ float g_gmax[BGR * HID];

// ---------------- helpers ----------------
__device__ __forceinline__ unsigned f2tf(float x) {
    unsigned u;
    asm("cvt.rna.tf32.f32 %0, %1;" : "=r"(u) : "f"(x));
    return u;
}

__device__ __forceinline__ void mma_tf32(float (&d)[4], const unsigned (&a)[4],
                                         const unsigned (&b)[2]) {
    asm volatile(
        "mma.sync.aligned.m16n8k8.row.col.f32.tf32.tf32.f32 "
        "{%0,%1,%2,%3}, {%4,%5,%6,%7}, {%8,%9}, {%0,%1,%2,%3};\n"
        : "+f"(d[0]), "+f"(d[1]), "+f"(d[2]), "+f"(d[3])
        : "r"(a[0]), "r"(a[1]), "r"(a[2]), "r"(a[3]), "r"(b[0]), "r"(b[1]));
}

// ---------------- init ----------------
__global__ void k_init() {
    int i = blockIdx.x * blockDim.x + threadIdx.x;
    if (i < NN) { g_cnt[i] = 0; g_fill[i] = 0; }
    if (i < BGR * HID) { g_gsum[i] = 0.f; g_gmax[i] = 0.f; }
}

// ---------------- CSR build ----------------
__global__ void k_hist(const int* __restrict__ ei) {
    int e = blockIdx.x * blockDim.x + threadIdx.x;
    if (e < EE) atomicAdd(&g_cnt[ei[EE + e]], 1);   // dst
}

// multi-block scan, phase 1: block-local exclusive scan + block total
__global__ __launch_bounds__(1024) void k_scan1() {
    __shared__ int wsum[32];
    int t = threadIdx.x, lane = t & 31, w = t >> 5;
    int i = blockIdx.x * 1024 + t;
    int v = (i < NN) ? g_cnt[i] : 0;
    int sv = v;
    #pragma unroll
    for (int off = 1; off < 32; off <<= 1) {
        int n = __shfl_up_sync(0xffffffffu, sv, off);
        if (lane >= off) sv += n;
    }
    if (lane == 31) wsum[w] = sv;
    __syncthreads();
    if (w == 0) {
        int s = wsum[lane];
        #pragma unroll
        for (int off = 1; off < 32; off <<= 1) {
            int n = __shfl_up_sync(0xffffffffu, s, off);
            if (lane >= off) s += n;
        }
        wsum[lane] = s;
    }
    __syncthreads();
    int pre = (w > 0) ? wsum[w - 1] : 0;
    if (i < NN) g_rowstart[i] = pre + sv - v;   // block-local exclusive
    if (t == 1023) g_blocksum[blockIdx.x] = pre + sv;
}

// phase 2: serial exclusive scan of 49 block sums (trivial)
__global__ void k_scan2(int nblk) {
    if (threadIdx.x == 0) {
        int run = 0;
        for (int b = 0; b < nblk; b++) {
            int v = g_blocksum[b];
            g_blocksum[b] = run;
            run += v;
        }
        g_rowstart[NN] = EE;
    }
}

// phase 3: add block offsets
__global__ __launch_bounds__(1024) void k_scan3() {
    int i = blockIdx.x * 1024 + threadIdx.x;
    if (i < NN) g_rowstart[i] += g_blocksum[blockIdx.x];
}

__global__ void k_fill(const int* __restrict__ ei) {
    int e = blockIdx.x * blockDim.x + threadIdx.x;
    if (e < EE) {
        int d = ei[EE + e];
        int pos = g_rowstart[d] + atomicAdd(&g_fill[d], 1);
        g_src[pos] = ei[e];   // src
    }
}

// ---------------- fused 4-weight tf32 tensor-core GEMM ----------------
__global__ __launch_bounds__(256) void k_gemm4_tc(
    const float* __restrict__ Xin, int layer2,
    const float* __restrict__ W0, const float* __restrict__ B0,
    const float* __restrict__ W1, const float* __restrict__ B1,
    const float* __restrict__ W2, const float* __restrict__ B2,
    const float* __restrict__ W3, const float* __restrict__ B3)
{
    __shared__ unsigned As[128][36];
    __shared__ unsigned Bsm[32][136];

    const float* X = layer2 ? (const float*)g_H1 : Xin;

    const float* W; const float* Bb; float* Out;
    switch (blockIdx.y) {
        case 0:  W = W0; Bb = B0; Out = g_Q; break;
        case 1:  W = W1; Bb = B1; Out = g_K; break;
        case 2:  W = W2; Bb = B2; Out = g_V; break;
        default: W = W3; Bb = B3; Out = g_S; break;
    }

    const int row0 = blockIdx.x * 128;
    const int tid = threadIdx.x;
    const int lane = tid & 31;
    const int w = tid >> 5;
    const int wm = w >> 1;
    const int wn = w & 1;
    const int g = lane >> 2;
    const int tig = lane & 3;

    float acc[2][8][4];
    #pragma unroll
    for (int a = 0; a < 2; a++)
        #pragma unroll
        for (int b = 0; b < 8; b++)
            #pragma unroll
            for (int c = 0; c < 4; c++) acc[a][b][c] = 0.f;

    for (int k0 = 0; k0 < 128; k0 += 32) {
        #pragma unroll
        for (int i = 0; i < 4; i++) {
            int lin = tid + i * 256;
            int m = lin >> 3;
            int kq = (lin & 7) * 4;
            int gm = row0 + m;
            float4 v = make_float4(0.f, 0.f, 0.f, 0.f);
            if (gm < NN) v = *(const float4*)(X + gm * 128 + k0 + kq);
            uint4 u;
            u.x = f2tf(v.x); u.y = f2tf(v.y); u.z = f2tf(v.z); u.w = f2tf(v.w);
            *(uint4*)&As[m][kq] = u;
        }
        #pragma unroll
        for (int i = 0; i < 4; i++) {
            int lin = tid + i * 256;
            int kq = lin >> 5;
            int n4 = (lin & 31) * 4;
            float4 v = *(const float4*)(W + (k0 + kq) * 128 + n4);
            uint4 u;
            u.x = f2tf(v.x); u.y = f2tf(v.y); u.z = f2tf(v.z); u.w = f2tf(v.w);
            *(uint4*)&Bsm[kq][n4] = u;
        }
        __syncthreads();

        #pragma unroll
        for (int kk = 0; kk < 32; kk += 8) {
            unsigned a[2][4];
            #pragma unroll
            for (int mt = 0; mt < 2; mt++) {
                int r = wm * 32 + mt * 16;
                a[mt][0] = As[r + g][kk + tig];
                a[mt][1] = As[r + g + 8][kk + tig];
                a[mt][2] = As[r + g][kk + tig + 4];
                a[mt][3] = As[r + g + 8][kk + tig + 4];
            }
            #pragma unroll
            for (int nt = 0; nt < 8; nt++) {
                unsigned b[2];
                int c = wn * 64 + nt * 8 + g;
                b[0] = Bsm[kk + tig][c];
                b[1] = Bsm[kk + tig + 4][c];
                mma_tf32(acc[0][nt], a[0], b);
                mma_tf32(acc[1][nt], a[1], b);
            }
        }
        __syncthreads();
    }

    #pragma unroll
    for (int nt = 0; nt < 8; nt++) {
        int col = wn * 64 + nt * 8 + 2 * tig;
        float2 bias2 = *(const float2*)(Bb + col);
        #pragma unroll
        for (int mt = 0; mt < 2; mt++) {
            int r0 = row0 + wm * 32 + mt * 16 + g;
            int r1 = r0 + 8;
            if (r0 < NN) {
                float2 o;
                o.x = acc[mt][nt][0] + bias2.x;
                o.y = acc[mt][nt][1] + bias2.y;
                *(float2*)(Out + r0 * 128 + col) = o;
            }
            if (r1 < NN) {
                float2 o;
                o.x = acc[mt][nt][2] + bias2.x;
                o.y = acc[mt][nt][3] + bias2.y;
                *(float2*)(Out + r1 * 128 + col) = o;
            }
        }
    }
}

// ---------------- attention: warp/dst, online softmax, 2 edges/step --------
__global__ __launch_bounds__(256) void k_attn(int out_sel)
{
    int gw = (blockIdx.x * blockDim.x + threadIdx.x) >> 5;
    int lane = threadIdx.x & 31;
    if (gw >= NN) return;
    const int i = gw;
    const int co = lane * 4;

    const float* __restrict__ Qb = g_Q;
    const float* __restrict__ Kb = g_K;
    const float* __restrict__ Vb = g_V;
    const float* __restrict__ Sb = g_S;
    float* __restrict__ Hb = out_sel ? g_H2 : g_H1;

    float4 q = *(const float4*)(Qb + i * 128 + co);
    int e0 = g_rowstart[i], e1 = g_rowstart[i + 1];

    float m = -1e30f, s = 0.f;
    float4 acc = make_float4(0.f, 0.f, 0.f, 0.f);
    const float rsC = 0.17677669529663687f;   // 1/sqrt(32)

    if (e0 < e1) {
        int sA = g_src[e0];
        int sB = (e0 + 1 < e1) ? g_src[e0 + 1] : sA;
        float4 kA = *(const float4*)(Kb + sA * 128 + co);
        float4 vA = *(const float4*)(Vb + sA * 128 + co);
        float4 kB = *(const float4*)(Kb + sB * 128 + co);
        float4 vB = *(const float4*)(Vb + sB * 128 + co);

        for (int e = e0; e < e1; e += 2) {
            bool hasB = (e + 1 < e1);

            // prefetch next pair
            int pA = (e + 2 < e1) ? g_src[e + 2] : sA;
            int pB = (e + 3 < e1) ? g_src[e + 3] : pA;
            float4 nkA = *(const float4*)(Kb + pA * 128 + co);
            float4 nvA = *(const float4*)(Vb + pA * 128 + co);
            float4 nkB = *(const float4*)(Kb + pB * 128 + co);
            float4 nvB = *(const float4*)(Vb + pB * 128 + co);

            // two independent logit reductions (shfl trees overlap)
            float dA = q.x * kA.x + q.y * kA.y + q.z * kA.z + q.w * kA.w;
            float dB = q.x * kB.x + q.y * kB.y + q.z * kB.z + q.w * kB.w;
            dA += __shfl_xor_sync(0xffffffffu, dA, 1);
            dB += __shfl_xor_sync(0xffffffffu, dB, 1);
            dA += __shfl_xor_sync(0xffffffffu, dA, 2);
            dB += __shfl_xor_sync(0xffffffffu, dB, 2);
            dA += __shfl_xor_sync(0xffffffffu, dA, 4);
            dB += __shfl_xor_sync(0xffffffffu, dB, 4);

            float aA = dA * rsC;
            float aB = hasB ? dB * rsC : -1e30f;

            float nm = fmaxf(m, fmaxf(aA, aB));
            float sc = __expf(m - nm);
            float wA = __expf(aA - nm);
            float wB = hasB ? __expf(aB - nm) : 0.f;
            s = fmaf(s, sc, wA + wB);
            acc.x = fmaf(wB, vB.x, fmaf(wA, vA.x, acc.x * sc));
            acc.y = fmaf(wB, vB.y, fmaf(wA, vA.y, acc.y * sc));
            acc.z = fmaf(wB, vB.z, fmaf(wA, vA.z, acc.z * sc));
            acc.w = fmaf(wB, vB.w, fmaf(wA, vA.w, acc.w * sc));
            m = nm;

            kA = nkA; vA = nvA; kB = nkB; vB = nvB;
        }
    }

    float inv = 1.f / (s + 1e-16f);
    float4 sk = *(const float4*)(Sb + i * 128 + co);
    float4 o;
    o.x = fmaxf(fmaf(acc.x, inv, sk.x), 0.f);
    o.y = fmaxf(fmaf(acc.y, inv, sk.y), 0.f);
    o.z = fmaxf(fmaf(acc.z, inv, sk.z), 0.f);
    o.w = fmaxf(fmaf(acc.w, inv, sk.w), 0.f);
    *(float4*)(Hb + i * 128 + co) = o;
}

// ---------------- pooling: batch is sorted; thread = channel ----------------
__global__ void k_pool(const int* __restrict__ batch) {
    int t = threadIdx.x;
    int n0 = blockIdx.x * 512;
    if (n0 >= NN) return;
    int n1 = n0 + 512; if (n1 > NN) n1 = NN;
    const float* __restrict__ Hf = g_H2;

    int cur = batch[n0];
    float sum = 0.f, mx = 0.f;
    for (int n = n0; n < n1; n++) {
        int b = batch[n];
        if (b != cur) {
            atomicAdd(&g_gsum[cur * 128 + t], sum);
            atomicMax((int*)&g_gmax[cur * 128 + t], __float_as_int(mx));
            sum = 0.f; mx = 0.f; cur = b;
        }
        float v = Hf[n * 128 + t];
        sum += v; mx = fmaxf(mx, v);
    }
    atomicAdd(&g_gsum[cur * 128 + t], sum);
    atomicMax((int*)&g_gmax[cur * 128 + t], __float_as_int(mx));
}

// ---------------- classifier ----------------
__global__ void k_cls(const float* __restrict__ Wlin, const float* __restrict__ blin,
                      float* __restrict__ out) {
    int t = threadIdx.x;
    if (t >= 128) return;
    int b = t >> 1, c = t & 1;
    float acc = blin[c];
    for (int j = 0; j < 128; j++) acc = fmaf(g_gsum[b * 128 + j], Wlin[j * 2 + c], acc);
    for (int j = 0; j < 128; j++) acc = fmaf(g_gmax[b * 128 + j], Wlin[(128 + j) * 2 + c], acc);
    out[b * 2 + c] = acc;
}

// ---------------- launch ----------------
extern "C" void kernel_launch(void* const* d_in, const int* in_sizes, int n_in,
                              void* d_out, int out_size)
{
    const float* x   = (const float*)d_in[0];
    const int* ei    = (const int*)d_in[1];
    const int* batch = (const int*)d_in[2];
    const float* Wq1 = (const float*)d_in[3];  const float* bq1 = (const float*)d_in[4];
    const float* Wk1 = (const float*)d_in[5];  const float* bk1 = (const float*)d_in[6];
    const float* Wv1 = (const float*)d_in[7];  const float* bv1 = (const float*)d_in[8];
    const float* Ws1 = (const float*)d_in[9];  const float* bs1 = (const float*)d_in[10];
    const float* Wq2 = (const float*)d_in[11]; const float* bq2 = (const float*)d_in[12];
    const float* Wk2 = (const float*)d_in[13]; const float* bk2 = (const float*)d_in[14];
    const float* Wv2 = (const float*)d_in[15]; const float* bv2 = (const float*)d_in[16];
    const float* Ws2 = (const float*)d_in[17]; const float* bs2 = (const float*)d_in[18];
    const float* Wlin = (const float*)d_in[19]; const float* blin = (const float*)d_in[20];
    float* out = (float*)d_out;

    const int SCAN_BLOCKS = (NN + 1023) / 1024;   // 49

    // CSR build + scratch init
    k_init<<<(NN + 255) / 256, 256>>>();
    k_hist<<<(EE + 255) / 256, 256>>>(ei);
    k_scan1<<<SCAN_BLOCKS, 1024>>>();
    k_scan2<<<1, 32>>>(SCAN_BLOCKS);
    k_scan3<<<SCAN_BLOCKS, 1024>>>();
    k_fill<<<(EE + 255) / 256, 256>>>(ei);

    dim3 gg((NN + 127) / 128, 4);

    // layer 1
    k_gemm4_tc<<<gg, 256>>>(x, 0, Wq1, bq1, Wk1, bk1, Wv1, bv1, Ws1, bs1);
    k_attn<<<(NN + 7) / 8, 256>>>(0);

    // layer 2
    k_gemm4_tc<<<gg, 256>>>(x, 1, Wq2, bq2, Wk2, bk2, Wv2, bv2, Ws2, bs2);
    k_attn<<<(NN + 7) / 8, 256>>>(1);

    // pooling + classifier
    k_pool<<<(NN + 511) / 512, 128>>>(batch);
    k_cls<<<1, 128>>>(Wlin, blin, out);
}

// round 5
// speedup vs baseline: 1.6404x; 1.0289x over previous
#include <cuda_runtime.h>
#include <cuda_fp16.h>
#include <math.h>

#define NN 50000
#define EE 800000
#define HID 128
#define BGR 64

// ---------------- scratch (static __device__, no allocation) ----------------
__device__ float  g_Q[NN * HID];
__device__ __half g_Kh[NN * HID];
__device__ __half g_Vh[NN * HID];
__device__ float  g_S[NN * HID];
__device__ float  g_H1[NN * HID];
__device__ float  g_H2[NN * HID];

__device__ int g_rowstart[NN + 1];
__device__ int g_cnt[NN];
__device__ int g_fill[NN];
__device__ int g_src[EE];
__device__ int g_blocksum[64];

__device__ float g_gsum[BGR * HID];
__device__ float g_gmax[BGR * HID];

// ---------------- helpers ----------------
__device__ __forceinline__ unsigned f2tf(float x) {
    unsigned u;
    asm("cvt.rna.tf32.f32 %0, %1;" : "=r"(u) : "f"(x));
    return u;
}

__device__ __forceinline__ void mma_tf32(float (&d)[4], const unsigned (&a)[4],
                                         const unsigned (&b)[2]) {
    asm volatile(
        "mma.sync.aligned.m16n8k8.row.col.f32.tf32.tf32.f32 "
        "{%0,%1,%2,%3}, {%4,%5,%6,%7}, {%8,%9}, {%0,%1,%2,%3};\n"
        : "+f"(d[0]), "+f"(d[1]), "+f"(d[2]), "+f"(d[3])
        : "r"(a[0]), "r"(a[1]), "r"(a[2]), "r"(a[3]), "r"(b[0]), "r"(b[1]));
}

// load 4 halves (lane's 4 channels) and convert to float4
__device__ __forceinline__ float4 ldh4(const __half* p) {
    uint2 u = *(const uint2*)p;
    __half2 h0 = *reinterpret_cast<__half2*>(&u.x);
    __half2 h1 = *reinterpret_cast<__half2*>(&u.y);
    float2 f0 = __half22float2(h0);
    float2 f1 = __half22float2(h1);
    return make_float4(f0.x, f0.y, f1.x, f1.y);
}

// ---------------- init ----------------
__global__ void k_init() {
    int i = blockIdx.x * blockDim.x + threadIdx.x;
    if (i < NN) { g_cnt[i] = 0; g_fill[i] = 0; }
    if (i < BGR * HID) { g_gsum[i] = 0.f; g_gmax[i] = 0.f; }
}

// ---------------- CSR build ----------------
__global__ void k_hist(const int* __restrict__ ei) {
    int e = blockIdx.x * blockDim.x + threadIdx.x;
    if (e < EE) atomicAdd(&g_cnt[ei[EE + e]], 1);   // dst
}

__global__ __launch_bounds__(1024) void k_scan1() {
    __shared__ int wsum[32];
    int t = threadIdx.x, lane = t & 31, w = t >> 5;
    int i = blockIdx.x * 1024 + t;
    int v = (i < NN) ? g_cnt[i] : 0;
    int sv = v;
    #pragma unroll
    for (int off = 1; off < 32; off <<= 1) {
        int n = __shfl_up_sync(0xffffffffu, sv, off);
        if (lane >= off) sv += n;
    }
    if (lane == 31) wsum[w] = sv;
    __syncthreads();
    if (w == 0) {
        int s = wsum[lane];
        #pragma unroll
        for (int off = 1; off < 32; off <<= 1) {
            int n = __shfl_up_sync(0xffffffffu, s, off);
            if (lane >= off) s += n;
        }
        wsum[lane] = s;
    }
    __syncthreads();
    int pre = (w > 0) ? wsum[w - 1] : 0;
    if (i < NN) g_rowstart[i] = pre + sv - v;
    if (t == 1023) g_blocksum[blockIdx.x] = pre + sv;
}

// 64-thread shfl scan of <=64 block sums
__global__ void k_scan2(int nblk) {
    __shared__ int w0tot;
    int t = threadIdx.x, lane = t & 31, w = t >> 5;
    int v = (t < nblk) ? g_blocksum[t] : 0;
    int s = v;
    #pragma unroll
    for (int off = 1; off < 32; off <<= 1) {
        int n = __shfl_up_sync(0xffffffffu, s, off);
        if (lane >= off) s += n;
    }
    if (w == 0 && lane == 31) w0tot = s;
    __syncthreads();
    if (w == 1) s += w0tot;
    if (t < nblk) g_blocksum[t] = s - v;      // exclusive
    if (t == 0) g_rowstart[NN] = EE;
}

__global__ __launch_bounds__(1024) void k_scan3() {
    int i = blockIdx.x * 1024 + threadIdx.x;
    if (i < NN) g_rowstart[i] += g_blocksum[blockIdx.x];
}

__global__ void k_fill(const int* __restrict__ ei) {
    int e = blockIdx.x * blockDim.x + threadIdx.x;
    if (e < EE) {
        int d = ei[EE + e];
        int pos = g_rowstart[d] + atomicAdd(&g_fill[d], 1);
        g_src[pos] = ei[e];   // src
    }
}

// ---------------- fused 4-weight tf32 tensor-core GEMM ----------------
// y=0 -> Q (fp32), y=1 -> K (fp16), y=2 -> V (fp16), y=3 -> S (fp32)
__global__ __launch_bounds__(256) void k_gemm4_tc(
    const float* __restrict__ Xin, int layer2,
    const float* __restrict__ W0, const float* __restrict__ B0,
    const float* __restrict__ W1, const float* __restrict__ B1,
    const float* __restrict__ W2, const float* __restrict__ B2,
    const float* __restrict__ W3, const float* __restrict__ B3)
{
    __shared__ unsigned As[128][36];
    __shared__ unsigned Bsm[32][136];

    const float* X = layer2 ? (const float*)g_H1 : Xin;

    const float* W; const float* Bb; float* OutF = 0; __half* OutH = 0;
    switch (blockIdx.y) {
        case 0:  W = W0; Bb = B0; OutF = g_Q;  break;
        case 1:  W = W1; Bb = B1; OutH = g_Kh; break;
        case 2:  W = W2; Bb = B2; OutH = g_Vh; break;
        default: W = W3; Bb = B3; OutF = g_S;  break;
    }

    const int row0 = blockIdx.x * 128;
    const int tid = threadIdx.x;
    const int lane = tid & 31;
    const int w = tid >> 5;
    const int wm = w >> 1;
    const int wn = w & 1;
    const int g = lane >> 2;
    const int tig = lane & 3;

    float acc[2][8][4];
    #pragma unroll
    for (int a = 0; a < 2; a++)
        #pragma unroll
        for (int b = 0; b < 8; b++)
            #pragma unroll
            for (int c = 0; c < 4; c++) acc[a][b][c] = 0.f;

    for (int k0 = 0; k0 < 128; k0 += 32) {
        #pragma unroll
        for (int i = 0; i < 4; i++) {
            int lin = tid + i * 256;
            int m = lin >> 3;
            int kq = (lin & 7) * 4;
            int gm = row0 + m;
            float4 v = make_float4(0.f, 0.f, 0.f, 0.f);
            if (gm < NN) v = *(const float4*)(X + gm * 128 + k0 + kq);
            uint4 u;
            u.x = f2tf(v.x); u.y = f2tf(v.y); u.z = f2tf(v.z); u.w = f2tf(v.w);
            *(uint4*)&As[m][kq] = u;
        }
        #pragma unroll
        for (int i = 0; i < 4; i++) {
            int lin = tid + i * 256;
            int kq = lin >> 5;
            int n4 = (lin & 31) * 4;
            float4 v = *(const float4*)(W + (k0 + kq) * 128 + n4);
            uint4 u;
            u.x = f2tf(v.x); u.y = f2tf(v.y); u.z = f2tf(v.z); u.w = f2tf(v.w);
            *(uint4*)&Bsm[kq][n4] = u;
        }
        __syncthreads();

        #pragma unroll
        for (int kk = 0; kk < 32; kk += 8) {
            unsigned a[2][4];
            #pragma unroll
            for (int mt = 0; mt < 2; mt++) {
                int r = wm * 32 + mt * 16;
                a[mt][0] = As[r + g][kk + tig];
                a[mt][1] = As[r + g + 8][kk + tig];
                a[mt][2] = As[r + g][kk + tig + 4];
                a[mt][3] = As[r + g + 8][kk + tig + 4];
            }
            #pragma unroll
            for (int nt = 0; nt < 8; nt++) {
                unsigned b[2];
                int c = wn * 64 + nt * 8 + g;
                b[0] = Bsm[kk + tig][c];
                b[1] = Bsm[kk + tig + 4][c];
                mma_tf32(acc[0][nt], a[0], b);
                mma_tf32(acc[1][nt], a[1], b);
            }
        }
        __syncthreads();
    }

    bool isHalf = (OutH != 0);
    #pragma unroll
    for (int nt = 0; nt < 8; nt++) {
        int col = wn * 64 + nt * 8 + 2 * tig;
        float2 bias2 = *(const float2*)(Bb + col);
        #pragma unroll
        for (int mt = 0; mt < 2; mt++) {
            int r0 = row0 + wm * 32 + mt * 16 + g;
            int r1 = r0 + 8;
            float2 o0, o1;
            o0.x = acc[mt][nt][0] + bias2.x;
            o0.y = acc[mt][nt][1] + bias2.y;
            o1.x = acc[mt][nt][2] + bias2.x;
            o1.y = acc[mt][nt][3] + bias2.y;
            if (isHalf) {
                if (r0 < NN) *(__half2*)(OutH + r0 * 128 + col) = __floats2half2_rn(o0.x, o0.y);
                if (r1 < NN) *(__half2*)(OutH + r1 * 128 + col) = __floats2half2_rn(o1.x, o1.y);
            } else {
                if (r0 < NN) *(float2*)(OutF + r0 * 128 + col) = o0;
                if (r1 < NN) *(float2*)(OutF + r1 * 128 + col) = o1;
            }
        }
    }
}

// ---------------- attention: warp/dst, online softmax, 4 edges/step --------
__global__ __launch_bounds__(256) void k_attn(int out_sel)
{
    int gw = (blockIdx.x * blockDim.x + threadIdx.x) >> 5;
    int lane = threadIdx.x & 31;
    if (gw >= NN) return;
    const int i = gw;
    const int co = lane * 4;

    const float*  __restrict__ Qb = g_Q;
    const __half* __restrict__ Kb = g_Kh;
    const __half* __restrict__ Vb = g_Vh;
    const float*  __restrict__ Sb = g_S;
    float* __restrict__ Hb = out_sel ? g_H2 : g_H1;

    float4 q = *(const float4*)(Qb + i * 128 + co);
    int e0 = g_rowstart[i], e1 = g_rowstart[i + 1];

    float m = -1e30f, s = 0.f;
    float4 acc = make_float4(0.f, 0.f, 0.f, 0.f);
    const float rsC = 0.17677669529663687f;   // 1/sqrt(32)

    for (int base = e0; base < e1; base += 4) {
        // clamped edge indices (tail edges repeat the last valid one; masked below)
        int j0 = base;
        int j1 = (base + 1 < e1) ? base + 1 : e1 - 1;
        int j2 = (base + 2 < e1) ? base + 2 : e1 - 1;
        int j3 = (base + 3 < e1) ? base + 3 : e1 - 1;
        int s0 = g_src[j0], s1 = g_src[j1], s2 = g_src[j2], s3 = g_src[j3];

        // issue all 8 loads before any compute
        float4 k0 = ldh4(Kb + s0 * 128 + co);
        float4 k1 = ldh4(Kb + s1 * 128 + co);
        float4 k2 = ldh4(Kb + s2 * 128 + co);
        float4 k3 = ldh4(Kb + s3 * 128 + co);
        float4 v0 = ldh4(Vb + s0 * 128 + co);
        float4 v1 = ldh4(Vb + s1 * 128 + co);
        float4 v2 = ldh4(Vb + s2 * 128 + co);
        float4 v3 = ldh4(Vb + s3 * 128 + co);

        float d0 = q.x * k0.x + q.y * k0.y + q.z * k0.z + q.w * k0.w;
        float d1 = q.x * k1.x + q.y * k1.y + q.z * k1.z + q.w * k1.w;
        float d2 = q.x * k2.x + q.y * k2.y + q.z * k2.z + q.w * k2.w;
        float d3 = q.x * k3.x + q.y * k3.y + q.z * k3.z + q.w * k3.w;

        d0 += __shfl_xor_sync(0xffffffffu, d0, 1);
        d1 += __shfl_xor_sync(0xffffffffu, d1, 1);
        d2 += __shfl_xor_sync(0xffffffffu, d2, 1);
        d3 += __shfl_xor_sync(0xffffffffu, d3, 1);
        d0 += __shfl_xor_sync(0xffffffffu, d0, 2);
        d1 += __shfl_xor_sync(0xffffffffu, d1, 2);
        d2 += __shfl_xor_sync(0xffffffffu, d2, 2);
        d3 += __shfl_xor_sync(0xffffffffu, d3, 2);
        d0 += __shfl_xor_sync(0xffffffffu, d0, 4);
        d1 += __shfl_xor_sync(0xffffffffu, d1, 4);
        d2 += __shfl_xor_sync(0xffffffffu, d2, 4);
        d3 += __shfl_xor_sync(0xffffffffu, d3, 4);

        float a0 = d0 * rsC;
        float a1 = (base + 1 < e1) ? d1 * rsC : -1e30f;
        float a2 = (base + 2 < e1) ? d2 * rsC : -1e30f;
        float a3 = (base + 3 < e1) ? d3 * rsC : -1e30f;

        float nm = fmaxf(fmaxf(m, fmaxf(a0, a1)), fmaxf(a2, a3));
        float sc = __expf(m - nm);
        float w0 = __expf(a0 - nm);
        float w1 = __expf(a1 - nm);
        float w2 = __expf(a2 - nm);
        float w3 = __expf(a3 - nm);
        s = fmaf(s, sc, (w0 + w1) + (w2 + w3));
        acc.x = fmaf(w3, v3.x, fmaf(w2, v2.x, fmaf(w1, v1.x, fmaf(w0, v0.x, acc.x * sc))));
        acc.y = fmaf(w3, v3.y, fmaf(w2, v2.y, fmaf(w1, v1.y, fmaf(w0, v0.y, acc.y * sc))));
        acc.z = fmaf(w3, v3.z, fmaf(w2, v2.z, fmaf(w1, v1.z, fmaf(w0, v0.z, acc.z * sc))));
        acc.w = fmaf(w3, v3.w, fmaf(w2, v2.w, fmaf(w1, v1.w, fmaf(w0, v0.w, acc.w * sc))));
        m = nm;
    }

    float inv = 1.f / (s + 1e-16f);
    float4 sk = *(const float4*)(Sb + i * 128 + co);
    float4 o;
    o.x = fmaxf(fmaf(acc.x, inv, sk.x), 0.f);
    o.y = fmaxf(fmaf(acc.y, inv, sk.y), 0.f);
    o.z = fmaxf(fmaf(acc.z, inv, sk.z), 0.f);
    o.w = fmaxf(fmaf(acc.w, inv, sk.w), 0.f);
    *(float4*)(Hb + i * 128 + co) = o;
}

// ---------------- pooling ----------------
__global__ void k_pool(const int* __restrict__ batch) {
    int t = threadIdx.x;
    int n0 = blockIdx.x * 512;
    if (n0 >= NN) return;
    int n1 = n0 + 512; if (n1 > NN) n1 = NN;
    const float* __restrict__ Hf = g_H2;

    int cur = batch[n0];
    float sum = 0.f, mx = 0.f;
    for (int n = n0; n < n1; n++) {
        int b = batch[n];
        if (b != cur) {
            atomicAdd(&g_gsum[cur * 128 + t], sum);
            atomicMax((int*)&g_gmax[cur * 128 + t], __float_as_int(mx));
            sum = 0.f; mx = 0.f; cur = b;
        }
        float v = Hf[n * 128 + t];
        sum += v; mx = fmaxf(mx, v);
    }
    atomicAdd(&g_gsum[cur * 128 + t], sum);
    atomicMax((int*)&g_gmax[cur * 128 + t], __float_as_int(mx));
}

// ---------------- classifier ----------------
__global__ void k_cls(const float* __restrict__ Wlin, const float* __restrict__ blin,
                      float* __restrict__ out) {
    int t = threadIdx.x;
    if (t >= 128) return;
    int b = t >> 1, c = t & 1;
    float acc = blin[c];
    for (int j = 0; j < 128; j++) acc = fmaf(g_gsum[b * 128 + j], Wlin[j * 2 + c], acc);
    for (int j = 0; j < 128; j++) acc = fmaf(g_gmax[b * 128 + j], Wlin[(128 + j) * 2 + c], acc);
    out[b * 2 + c] = acc;
}

// ---------------- launch ----------------
extern "C" void kernel_launch(void* const* d_in, const int* in_sizes, int n_in,
                              void* d_out, int out_size)
{
    const float* x   = (const float*)d_in[0];
    const int* ei    = (const int*)d_in[1];
    const int* batch = (const int*)d_in[2];
    const float* Wq1 = (const float*)d_in[3];  const float* bq1 = (const float*)d_in[4];
    const float* Wk1 = (const float*)d_in[5];  const float* bk1 = (const float*)d_in[6];
    const float* Wv1 = (const float*)d_in[7];  const float* bv1 = (const float*)d_in[8];
    const float* Ws1 = (const float*)d_in[9];  const float* bs1 = (const float*)d_in[10];
    const float* Wq2 = (const float*)d_in[11]; const float* bq2 = (const float*)d_in[12];
    const float* Wk2 = (const float*)d_in[13]; const float* bk2 = (const float*)d_in[14];
    const float* Wv2 = (const float*)d_in[15]; const float* bv2 = (const float*)d_in[16];
    const float* Ws2 = (const float*)d_in[17]; const float* bs2 = (const float*)d_in[18];
    const float* Wlin = (const float*)d_in[19]; const float* blin = (const float*)d_in[20];
    float* out = (float*)d_out;

    const int SCAN_BLOCKS = (NN + 1023) / 1024;   // 49

    k_init<<<(NN + 255) / 256, 256>>>();
    k_hist<<<(EE + 255) / 256, 256>>>(ei);
    k_scan1<<<SCAN_BLOCKS, 1024>>>();
    k_scan2<<<1, 64>>>(SCAN_BLOCKS);
    k_scan3<<<SCAN_BLOCKS, 1024>>>();
    k_fill<<<(EE + 255) / 256, 256>>>(ei);

    dim3 gg((NN + 127) / 128, 4);

    // layer 1
    k_gemm4_tc<<<gg, 256>>>(x, 0, Wq1, bq1, Wk1, bk1, Wv1, bv1, Ws1, bs1);
    k_attn<<<(NN + 7) / 8, 256>>>(0);

    // layer 2
    k_gemm4_tc<<<gg, 256>>>(x, 1, Wq2, bq2, Wk2, bk2, Wv2, bv2, Ws2, bs2);
    k_attn<<<(NN + 7) / 8, 256>>>(1);

    // pooling + classifier
    k_pool<<<(NN + 511) / 512, 128>>>(batch);
    k_cls<<<1, 128>>>(Wlin, blin, out);
}